// round 9
// baseline (speedup 1.0000x reference)
#include <cuda_runtime.h>
#include <cuda_bf16.h>
#include <math.h>
#include <stdint.h>

#define DIMC   1792
#define M_TOT  16384        // 4 * 64 * 64
#define NCENT  4096
#define HW     4096
#define NB_D   32           // dist n-tiles of 128
#define NB_P   14           // phi  n-tiles of 128
#define KSTEPS 28           // phi: 1792 / 64 (bf16, 128B k-chunks)
#define KSTEPS_D 14         // dist: 1792 / 128 (int8, 128B k-chunks)

// ---------------- scratch ---------------------------------------------------
__device__ __align__(1024) __nv_bfloat16 g_sample_t[(size_t)M_TOT * DIMC];
__device__ __align__(1024) __nv_bfloat16 g_phi_bf[(size_t)M_TOT * DIMC];
__device__ __align__(1024) __nv_bfloat16 g_Ct[(size_t)NCENT * DIMC];
__device__ __align__(1024) __nv_bfloat16 g_Wbf[(size_t)DIMC * DIMC];
__device__ __align__(1024) int8_t g_phi_q[(size_t)M_TOT * DIMC];
__device__ __align__(1024) int8_t g_Cq[(size_t)NCENT * DIMC];
__device__ float g_sphi[M_TOT];
__device__ float g_scC[NCENT];
__device__ float g_feat2[M_TOT];
__device__ float g_cnorm[NCENT];
__device__ float g_cand[(size_t)M_TOT * NB_D * 6];
__device__ float g_losspart[M_TOT];

// ---------------- helpers ----------------------------------------------------
__device__ __forceinline__ uint32_t smem_u32(const void* p) {
    uint32_t a;
    asm("{ .reg .u64 t; cvta.to.shared.u64 t, %1; cvt.u32.u64 %0, t; }" : "=r"(a) : "l"(p));
    return a;
}
__device__ __forceinline__ void cp16(uint32_t dst, const void* src) {
    asm volatile("cp.async.cg.shared.global [%0], [%1], 16;" :: "r"(dst), "l"(src));
}
__device__ __forceinline__ void insert6(float (&t)[6], float v) {
    if (v < t[5]) {
        t[5] = v;
        #pragma unroll
        for (int j = 5; j > 0; --j)
            if (t[j] < t[j-1]) { float tmp = t[j-1]; t[j-1] = t[j]; t[j] = tmp; }
    }
}

// stage: A(128 rows x 128B) + B(128 rows x 128B) = 32KB; 3 stages = 96KB
#define STG_BYTES 32768
#define B_OFF     16384
#define DYN_SMEM  (3 * STG_BYTES)
// full SW128 swizzle: row r (0..127, 128B pitch), 16B-chunk c (0..7)
__device__ __forceinline__ uint32_t swz(int r, int c) {
    return (uint32_t)(r * 128 + ((c ^ (r & 7)) * 16));
}

// generic 128x128B-per-stage loader; rowBytes = row stride of src in bytes
__device__ __forceinline__ void load_stage(uint32_t sb, int s,
                                           const char* A, const char* B,
                                           int k0bytes, int tid) {
    uint32_t abase = sb + s * STG_BYTES;
    uint32_t bbase = abase + B_OFF;
    #pragma unroll
    for (int i = 0; i < 4; ++i) {
        int slot = tid + i * 256;
        int r = slot >> 3, c = slot & 7;
        cp16(abase + swz(r, c), A + (size_t)r * (DIMC * 2) + k0bytes + c * 16);
    }
    #pragma unroll
    for (int i = 0; i < 4; ++i) {
        int slot = tid + i * 256;
        int r = slot >> 3, c = slot & 7;
        cp16(bbase + swz(r, c), B + (size_t)r * (DIMC * 2) + k0bytes + c * 16);
    }
    asm volatile("cp.async.commit_group;" ::: "memory");
}

__device__ __forceinline__ void load_stage8(uint32_t sb, int s,
                                            const char* A, const char* B,
                                            int k0bytes, int tid) {
    uint32_t abase = sb + s * STG_BYTES;
    uint32_t bbase = abase + B_OFF;
    #pragma unroll
    for (int i = 0; i < 4; ++i) {
        int slot = tid + i * 256;
        int r = slot >> 3, c = slot & 7;
        cp16(abase + swz(r, c), A + (size_t)r * DIMC + k0bytes + c * 16);
    }
    #pragma unroll
    for (int i = 0; i < 4; ++i) {
        int slot = tid + i * 256;
        int r = slot >> 3, c = slot & 7;
        cp16(bbase + swz(r, c), B + (size_t)r * DIMC + k0bytes + c * 16);
    }
    asm volatile("cp.async.commit_group;" ::: "memory");
}

// ---------------- bf16 GEMM: 128x128 tile, 8 warps (32x64), K=1792 -----------
__device__ __forceinline__ void gemm_bf16(const __nv_bfloat16* A,
                                          const __nv_bfloat16* B,
                                          uint32_t sb,
                                          float (&acc)[2][8][4]) {
    int tid = threadIdx.x, lane = tid & 31, w = tid >> 5;
    int wm = w & 3, wn = w >> 2;

    load_stage(sb, 0, (const char*)A, (const char*)B, 0, tid);
    load_stage(sb, 1, (const char*)A, (const char*)B, 128, tid);
    asm volatile("cp.async.wait_group 1;" ::: "memory");
    __syncthreads();

    for (int kt = 0; kt < KSTEPS; ++kt) {
        int s = kt % 3;
        if (kt + 2 < KSTEPS)
            load_stage(sb, (kt + 2) % 3, (const char*)A, (const char*)B,
                       (kt + 2) * 128, tid);

        uint32_t abase = sb + s * STG_BYTES;
        uint32_t bbase = abase + B_OFF;

        #pragma unroll
        for (int ks = 0; ks < 4; ++ks) {
            uint32_t afr[2][4];
            #pragma unroll
            for (int mi = 0; mi < 2; ++mi) {
                int r = wm * 32 + mi * 16 + (lane & 15);
                int c = ks * 2 + (lane >> 4);
                asm volatile("ldmatrix.sync.aligned.m8n8.x4.shared.b16 {%0,%1,%2,%3}, [%4];"
                             : "=r"(afr[mi][0]), "=r"(afr[mi][1]),
                               "=r"(afr[mi][2]), "=r"(afr[mi][3])
                             : "r"(abase + swz(r, c)));
            }
            uint32_t bfr[8][2];
            #pragma unroll
            for (int nq = 0; nq < 4; ++nq) {
                int q = lane >> 3;
                int r = wn * 64 + nq * 16 + (q >> 1) * 8 + (lane & 7);
                int c = ks * 2 + (q & 1);
                asm volatile("ldmatrix.sync.aligned.m8n8.x4.shared.b16 {%0,%1,%2,%3}, [%4];"
                             : "=r"(bfr[nq*2][0]), "=r"(bfr[nq*2][1]),
                               "=r"(bfr[nq*2+1][0]), "=r"(bfr[nq*2+1][1])
                             : "r"(bbase + swz(r, c)));
            }
            #pragma unroll
            for (int mi = 0; mi < 2; ++mi)
                #pragma unroll
                for (int ni = 0; ni < 8; ++ni)
                    asm volatile(
                        "mma.sync.aligned.m16n8k16.row.col.f32.bf16.bf16.f32 "
                        "{%0,%1,%2,%3}, {%4,%5,%6,%7}, {%8,%9}, {%0,%1,%2,%3};"
                        : "+f"(acc[mi][ni][0]), "+f"(acc[mi][ni][1]),
                          "+f"(acc[mi][ni][2]), "+f"(acc[mi][ni][3])
                        : "r"(afr[mi][0]), "r"(afr[mi][1]),
                          "r"(afr[mi][2]), "r"(afr[mi][3]),
                          "r"(bfr[ni][0]), "r"(bfr[ni][1]));
        }
        asm volatile("cp.async.wait_group 1;" ::: "memory");
        __syncthreads();
    }
}

// ---------------- int8 GEMM: 128x128 tile, 8 warps (32x64), K=1792 -----------
__device__ __forceinline__ void gemm_s8(const int8_t* A, const int8_t* B,
                                        uint32_t sb, int (&acc)[2][8][4]) {
    int tid = threadIdx.x, lane = tid & 31, w = tid >> 5;
    int wm = w & 3, wn = w >> 2;

    load_stage8(sb, 0, (const char*)A, (const char*)B, 0, tid);
    load_stage8(sb, 1, (const char*)A, (const char*)B, 128, tid);
    asm volatile("cp.async.wait_group 1;" ::: "memory");
    __syncthreads();

    for (int kt = 0; kt < KSTEPS_D; ++kt) {
        int s = kt % 3;
        if (kt + 2 < KSTEPS_D)
            load_stage8(sb, (kt + 2) % 3, (const char*)A, (const char*)B,
                        (kt + 2) * 128, tid);

        uint32_t abase = sb + s * STG_BYTES;
        uint32_t bbase = abase + B_OFF;

        #pragma unroll
        for (int ks = 0; ks < 4; ++ks) {
            uint32_t afr[2][4];
            #pragma unroll
            for (int mi = 0; mi < 2; ++mi) {
                int r = wm * 32 + mi * 16 + (lane & 15);
                int c = ks * 2 + (lane >> 4);
                asm volatile("ldmatrix.sync.aligned.m8n8.x4.shared.b16 {%0,%1,%2,%3}, [%4];"
                             : "=r"(afr[mi][0]), "=r"(afr[mi][1]),
                               "=r"(afr[mi][2]), "=r"(afr[mi][3])
                             : "r"(abase + swz(r, c)));
            }
            uint32_t bfr[8][2];
            #pragma unroll
            for (int nq = 0; nq < 4; ++nq) {
                int q = lane >> 3;
                int r = wn * 64 + nq * 16 + (q >> 1) * 8 + (lane & 7);
                int c = ks * 2 + (q & 1);
                asm volatile("ldmatrix.sync.aligned.m8n8.x4.shared.b16 {%0,%1,%2,%3}, [%4];"
                             : "=r"(bfr[nq*2][0]), "=r"(bfr[nq*2][1]),
                               "=r"(bfr[nq*2+1][0]), "=r"(bfr[nq*2+1][1])
                             : "r"(bbase + swz(r, c)));
            }
            #pragma unroll
            for (int mi = 0; mi < 2; ++mi)
                #pragma unroll
                for (int ni = 0; ni < 8; ++ni)
                    asm volatile(
                        "mma.sync.aligned.m16n8k32.row.col.s32.s8.s8.s32 "
                        "{%0,%1,%2,%3}, {%4,%5,%6,%7}, {%8,%9}, {%0,%1,%2,%3};"
                        : "+r"(acc[mi][ni][0]), "+r"(acc[mi][ni][1]),
                          "+r"(acc[mi][ni][2]), "+r"(acc[mi][ni][3])
                        : "r"(afr[mi][0]), "r"(afr[mi][1]),
                          "r"(afr[mi][2]), "r"(afr[mi][3]),
                          "r"(bfr[ni][0]), "r"(bfr[ni][1]));
        }
        asm volatile("cp.async.wait_group 1;" ::: "memory");
        __syncthreads();
    }
}

// ---------------- prepass kernels --------------------------------------------
__global__ void convert_W(const float* __restrict__ W) {
    int o = blockIdx.x;
    for (int c = threadIdx.x; c < DIMC; c += 256)
        g_Wbf[(size_t)o * DIMC + c] = __float2bfloat16(W[(size_t)o * 1794 + c]);
}

__global__ void transpose_sample(const float* __restrict__ S) {
    __shared__ float t[32][33];
    int b = blockIdx.z;
    int hw0 = blockIdx.x * 32, c0 = blockIdx.y * 32;
    int tx = threadIdx.x, ty = threadIdx.y;
    const float* src = S + ((size_t)b * DIMC + c0) * HW + hw0;
    #pragma unroll
    for (int i = 0; i < 4; ++i)
        t[ty + i * 8][tx] = src[(size_t)(ty + i * 8) * HW + tx];
    __syncthreads();
    __nv_bfloat16* dst = g_sample_t + ((size_t)b * HW + hw0) * DIMC + c0;
    #pragma unroll
    for (int i = 0; i < 4; ++i)
        dst[(size_t)(ty + i * 8) * DIMC + tx] = __float2bfloat16(t[tx][ty + i * 8]);
}

__global__ void transpose_C(const float* __restrict__ C) {
    __shared__ float t[32][33];
    int k0 = blockIdx.x * 32, c0 = blockIdx.y * 32;
    int tx = threadIdx.x, ty = threadIdx.y;
    #pragma unroll
    for (int i = 0; i < 4; ++i)
        t[ty + i * 8][tx] = C[(size_t)(c0 + ty + i * 8) * NCENT + k0 + tx];
    __syncthreads();
    #pragma unroll
    for (int i = 0; i < 4; ++i)
        g_Ct[(size_t)(k0 + ty + i * 8) * DIMC + c0 + tx] = __float2bfloat16(t[tx][ty + i * 8]);
}

// generic bf16-row -> int8 quantizer (warp per row): scale, q, feat2
__device__ __forceinline__ void quant_row(const __nv_bfloat16* src, int8_t* dst,
                                          float* scale_out, float* norm_out,
                                          int row, int lane) {
    const uint4* rp = (const uint4*)(src + (size_t)row * DIMC);   // 224 uint4
    uint4 v[7];
    #pragma unroll
    for (int i = 0; i < 7; ++i) v[i] = rp[lane + 32 * i];
    float mx = 0.f;
    #pragma unroll
    for (int i = 0; i < 7; ++i) {
        const __nv_bfloat162* h = (const __nv_bfloat162*)&v[i];
        #pragma unroll
        for (int j = 0; j < 4; ++j) {
            float2 fv = __bfloat1622float2(h[j]);
            mx = fmaxf(mx, fmaxf(fabsf(fv.x), fabsf(fv.y)));
        }
    }
    #pragma unroll
    for (int o = 16; o; o >>= 1) mx = fmaxf(mx, __shfl_xor_sync(0xffffffffu, mx, o));
    float mxs = fmaxf(mx, 1e-20f);
    float s = mxs * (1.f / 127.f);
    float inv = 127.f / mxs;
    float sq = 0.f;
    uint2* outp = (uint2*)(dst + (size_t)row * DIMC);             // 224 uint2
    #pragma unroll
    for (int i = 0; i < 7; ++i) {
        const __nv_bfloat162* h = (const __nv_bfloat162*)&v[i];
        uint32_t b0 = 0, b1 = 0;
        #pragma unroll
        for (int j = 0; j < 4; ++j) {
            float2 fv = __bfloat1622float2(h[j]);
            int q0 = __float2int_rn(fv.x * inv);
            int q1 = __float2int_rn(fv.y * inv);
            q0 = max(-127, min(127, q0));
            q1 = max(-127, min(127, q1));
            float d0 = q0 * s, d1 = q1 * s;
            sq += d0 * d0 + d1 * d1;
            uint32_t pk = ((uint32_t)(q0 & 0xFF)) | ((uint32_t)(q1 & 0xFF) << 8);
            if (j & 1) b1 |= pk << ((j >> 1) ? 16 : 16);   // j=1 -> b0 hi, j=3 -> b1 hi
            // handled explicitly below instead
        }
        // explicit packing (clearer): recompute
        uint32_t w0 = 0, w1 = 0;
        #pragma unroll
        for (int j = 0; j < 4; ++j) {
            float2 fv = __bfloat1622float2(h[j]);
            int q0 = max(-127, min(127, __float2int_rn(fv.x * inv)));
            int q1 = max(-127, min(127, __float2int_rn(fv.y * inv)));
            uint32_t pk = ((uint32_t)(q0 & 0xFF)) | ((uint32_t)(q1 & 0xFF) << 8);
            if (j < 2) w0 |= pk << (j * 16);
            else       w1 |= pk << ((j - 2) * 16);
        }
        outp[lane + 32 * i] = make_uint2(w0, w1);
        (void)b0; (void)b1;
    }
    #pragma unroll
    for (int o = 16; o; o >>= 1) sq += __shfl_xor_sync(0xffffffffu, sq, o);
    if (lane == 0) { scale_out[row] = s; norm_out[row] = sq; }
}

__global__ void quant_phi_k() {
    int w = threadIdx.x >> 5, lane = threadIdx.x & 31;
    quant_row(g_phi_bf, g_phi_q, g_sphi, g_feat2, blockIdx.x * 8 + w, lane);
}
__global__ void quant_C_k() {
    int w = threadIdx.x >> 5, lane = threadIdx.x & 31;
    quant_row(g_Ct, g_Cq, g_scC, g_cnorm, blockIdx.x * 8 + w, lane);
}

// ---------------- phi GEMM (coordconv 1x1), bf16 -------------------------------
__global__ __launch_bounds__(256, 2) void phi_mma(const float* __restrict__ W,
                                                  const float* __restrict__ bias) {
    extern __shared__ __align__(1024) unsigned char smem[];
    uint32_t sb = smem_u32(smem);
    const int n0 = blockIdx.x * 128;
    const int p0 = blockIdx.y * 128;

    float acc[2][8][4] = {};
    gemm_bf16(g_sample_t + (size_t)p0 * DIMC, g_Wbf + (size_t)n0 * DIMC, sb, acc);

    int tid = threadIdx.x, lane = tid & 31, w = tid >> 5;
    int wm = w & 3, wn = w >> 2, gid = lane >> 2, tq = lane & 3;

    float* smw = (float*)smem;            // [128]wx [128]wy [128]b
    if (tid < 128) {
        size_t col = (size_t)(n0 + tid);
        smw[tid]       = __ldg(&W[col * 1794 + 1792]);
        smw[128 + tid] = __ldg(&W[col * 1794 + 1793]);
        smw[256 + tid] = __ldg(&bias[col]);
    }
    __syncthreads();

    #pragma unroll
    for (int mi = 0; mi < 2; ++mi)
        #pragma unroll
        for (int hh = 0; hh < 2; ++hh) {
            int row = wm * 32 + mi * 16 + hh * 8 + gid;
            int p = p0 + row;
            int hw = p & 4095;
            float xx = -1.f + 2.f * (float)(hw & 63) * (1.f / 63.f);
            float yy = -1.f + 2.f * (float)(hw >> 6) * (1.f / 63.f);
            #pragma unroll
            for (int ni = 0; ni < 8; ++ni) {
                int ci = wn * 64 + ni * 8 + tq * 2;
                float v0 = acc[mi][ni][hh * 2]     + xx * smw[ci]   + yy * smw[128 + ci]   + smw[256 + ci];
                float v1 = acc[mi][ni][hh * 2 + 1] + xx * smw[ci+1] + yy * smw[128 + ci+1] + smw[256 + ci+1];
                __nv_bfloat162 bb = __floats2bfloat162_rn(v0, v1);
                *(uint32_t*)&g_phi_bf[(size_t)p * DIMC + n0 + ci] = *(uint32_t*)&bb;
            }
        }
}

// ---------------- dist GEMM (int8) + per-tile top-6 ----------------------------
__global__ __launch_bounds__(256, 2) void dist_mma() {
    extern __shared__ __align__(1024) unsigned char smem[];
    uint32_t sb = smem_u32(smem);
    const int nb = blockIdx.x;
    const int n0 = nb * 128;
    const int p0 = blockIdx.y * 128;

    int acc[2][8][4] = {};
    gemm_s8(g_phi_q + (size_t)p0 * DIMC, g_Cq + (size_t)n0 * DIMC, sb, acc);

    int tid = threadIdx.x, lane = tid & 31, w = tid >> 5;
    int wm = w & 3, wn = w >> 2, gid = lane >> 2, tq = lane & 3;

    float* smc = (float*)smem;                 // [128] cnorm
    float* sms = (float*)(smem + 512);         // [128] scC
    float* sm_t6 = (float*)(smem + 1024);      // [128][2][6]
    if (tid < 128) {
        smc[tid] = g_cnorm[n0 + tid];
        sms[tid] = g_scC[n0 + tid];
    }
    __syncthreads();

    #pragma unroll
    for (int mi = 0; mi < 2; ++mi)
        #pragma unroll
        for (int hh = 0; hh < 2; ++hh) {
            int row = wm * 32 + mi * 16 + hh * 8 + gid;
            float f2 = g_feat2[p0 + row];
            float spx2 = 2.f * g_sphi[p0 + row];
            float t6[6];
            #pragma unroll
            for (int j = 0; j < 6; ++j) t6[j] = 3.4e38f;
            #pragma unroll
            for (int ni = 0; ni < 8; ++ni) {
                int ci = wn * 64 + ni * 8 + tq * 2;
                insert6(t6, f2 + smc[ci]     - spx2 * sms[ci]     * (float)acc[mi][ni][hh * 2]);
                insert6(t6, f2 + smc[ci + 1] - spx2 * sms[ci + 1] * (float)acc[mi][ni][hh * 2 + 1]);
            }
            #pragma unroll
            for (int off = 1; off <= 2; off <<= 1) {
                float o6[6];
                #pragma unroll
                for (int j = 0; j < 6; ++j) o6[j] = __shfl_xor_sync(0xffffffffu, t6[j], off);
                #pragma unroll
                for (int j = 0; j < 6; ++j) insert6(t6, o6[j]);
            }
            if (tq == 0) {
                #pragma unroll
                for (int j = 0; j < 6; ++j) sm_t6[(row * 2 + wn) * 6 + j] = t6[j];
            }
        }
    __syncthreads();
    if (tid < 128) {
        float t6[6];
        #pragma unroll
        for (int j = 0; j < 6; ++j) t6[j] = 3.4e38f;
        #pragma unroll
        for (int v = 0; v < 12; ++v) insert6(t6, sm_t6[tid * 12 + v]);
        size_t base = ((size_t)(p0 + tid) * NB_D + nb) * 6;
        #pragma unroll
        for (int j = 0; j < 6; ++j) g_cand[base + j] = t6[j];
    }
}

// ---------------- topk merge + score + loss -----------------------------------
__global__ void topk_kernel(const float* __restrict__ r_in, float* __restrict__ out) {
    int warp = threadIdx.x >> 5;
    int lane = threadIdx.x & 31;
    int p = blockIdx.x * 4 + warp;
    const float* cand = g_cand + (size_t)p * (NB_D * 6);   // 192 values

    float t6[6];
    #pragma unroll
    for (int j = 0; j < 6; ++j) t6[j] = 3.4e38f;
    #pragma unroll
    for (int j = 0; j < 6; ++j) insert6(t6, cand[lane + 32 * j]);

    #pragma unroll
    for (int off = 16; off > 0; off >>= 1) {
        float o6[6];
        #pragma unroll
        for (int j = 0; j < 6; ++j) o6[j] = __shfl_xor_sync(0xffffffffu, t6[j], off);
        #pragma unroll
        for (int j = 0; j < 6; ++j) insert6(t6, o6[j]);
    }

    if (lane == 0) {
        float rr = r_in[0];
        float r2 = rr * rr;
        float d0 = sqrtf(fmaxf(t6[0], 0.f));
        float d1 = sqrtf(fmaxf(t6[1], 0.f));
        float d2 = sqrtf(fmaxf(t6[2], 0.f));
        float w0 = 1.f / (1.f + expf(d0 - d1) + expf(d0 - d2));
        out[1 + p] = w0 * d0;

        float att = fmaxf(t6[0] - r2, 0.f) + fmaxf(t6[1] - r2, 0.f) + fmaxf(t6[2] - r2, 0.f);
        float rep = fmaxf(r2 - t6[3] - 0.1f, 0.f) + fmaxf(r2 - t6[4] - 0.1f, 0.f)
                  + fmaxf(r2 - t6[5] - 0.1f, 0.f);
        g_losspart[p] = att + rep;
    }
}

__global__ void loss_kernel(float* __restrict__ out) {
    __shared__ float sbuf[256];
    float s = 0.f;
    for (int i = threadIdx.x; i < M_TOT; i += 256) s += g_losspart[i];
    sbuf[threadIdx.x] = s;
    __syncthreads();
    for (int o = 128; o > 0; o >>= 1) {
        if (threadIdx.x < o) sbuf[threadIdx.x] += sbuf[threadIdx.x + o];
        __syncthreads();
    }
    if (threadIdx.x == 0)
        out[0] = sbuf[0] * (1000.f / (float)(M_TOT * 3));
}

// ---------------- launcher ------------------------------------------------------
extern "C" void kernel_launch(void* const* d_in, const int* in_sizes, int n_in,
                              void* d_out, int out_size) {
    const float* sample = (const float*)d_in[0];
    const float* W      = (const float*)d_in[1];
    const float* bias   = (const float*)d_in[2];
    const float* C      = (const float*)d_in[3];
    const float* r      = (const float*)d_in[4];
    float* out = (float*)d_out;

    convert_W<<<DIMC, 256>>>(W);
    transpose_sample<<<dim3(HW / 32, DIMC / 32, 4), dim3(32, 8)>>>(sample);
    transpose_C<<<dim3(NCENT / 32, DIMC / 32), dim3(32, 8)>>>(C);
    quant_C_k<<<NCENT / 8, 256>>>();

    cudaFuncSetAttribute(phi_mma, cudaFuncAttributeMaxDynamicSharedMemorySize, DYN_SMEM);
    phi_mma<<<dim3(NB_P, M_TOT / 128), 256, DYN_SMEM>>>(W, bias);
    quant_phi_k<<<M_TOT / 8, 256>>>();

    cudaFuncSetAttribute(dist_mma, cudaFuncAttributeMaxDynamicSharedMemorySize, DYN_SMEM);
    dist_mma<<<dim3(NB_D, M_TOT / 128), 256, DYN_SMEM>>>();

    topk_kernel<<<M_TOT / 4, 128>>>(r, out);
    loss_kernel<<<1, 256>>>(out);
}

// round 10
// speedup vs baseline: 2.0712x; 2.0712x over previous
#include <cuda_runtime.h>
#include <cuda_bf16.h>
#include <math.h>
#include <stdint.h>

#define DIMC   1792
#define M_TOT  16384        // 4 * 64 * 64
#define NCENT  4096
#define HW     4096
#define NB_D   32           // dist n-tiles of 128
#define NB_P   14           // phi  n-tiles of 128
#define KSTEPS 28           // 1792 / 64

// ---------------- scratch ---------------------------------------------------
__device__ __align__(1024) __nv_bfloat16 g_sample_t[(size_t)M_TOT * DIMC];
__device__ __align__(1024) __nv_bfloat16 g_phi_bf[(size_t)M_TOT * DIMC];
__device__ __align__(1024) __nv_bfloat16 g_Ct[(size_t)NCENT * DIMC];
__device__ __align__(1024) __nv_bfloat16 g_Wbf[(size_t)DIMC * DIMC];
__device__ float g_feat2p[M_TOT * NB_P];
__device__ float g_feat2[M_TOT];
__device__ float g_cnorm[NCENT];
__device__ float g_cand[(size_t)M_TOT * NB_D * 6];
__device__ float g_losspart[M_TOT];

// ---------------- helpers ----------------------------------------------------
__device__ __forceinline__ uint32_t smem_u32(const void* p) {
    uint32_t a;
    asm("{ .reg .u64 t; cvta.to.shared.u64 t, %1; cvt.u32.u64 %0, t; }" : "=r"(a) : "l"(p));
    return a;
}
__device__ __forceinline__ void cp16(uint32_t dst, const void* src) {
    asm volatile("cp.async.cg.shared.global [%0], [%1], 16;" :: "r"(dst), "l"(src));
}
__device__ __forceinline__ void insert6(float (&t)[6], float v) {
    if (v < t[5]) {
        t[5] = v;
        #pragma unroll
        for (int j = 5; j > 0; --j)
            if (t[j] < t[j-1]) { float tmp = t[j-1]; t[j-1] = t[j]; t[j] = tmp; }
    }
}

// stage: A(128 rows x 128B) + B(128 rows x 128B) = 32KB; 3 stages = 96KB
#define STG_BYTES 32768
#define B_OFF     16384
#define DYN_SMEM  (3 * STG_BYTES)
// full SW128 swizzle: row r (0..127, 128B pitch), 16B-chunk c (0..7)
__device__ __forceinline__ uint32_t swz(int r, int c) {
    return (uint32_t)(r * 128 + ((c ^ (r & 7)) * 16));
}

__device__ __forceinline__ void load_stage(uint32_t sb, int s,
                                           const __nv_bfloat16* A,
                                           const __nv_bfloat16* B,
                                           int k0, int tid) {
    uint32_t abase = sb + s * STG_BYTES;
    uint32_t bbase = abase + B_OFF;
    #pragma unroll
    for (int i = 0; i < 4; ++i) {           // A: 128 rows x 128B
        int slot = tid + i * 256;
        int r = slot >> 3, c = slot & 7;
        cp16(abase + swz(r, c), (const char*)A + ((size_t)r * DIMC + k0 + c * 8) * 2);
    }
    #pragma unroll
    for (int i = 0; i < 4; ++i) {           // B: 128 rows x 128B
        int slot = tid + i * 256;
        int r = slot >> 3, c = slot & 7;
        cp16(bbase + swz(r, c), (const char*)B + ((size_t)r * DIMC + k0 + c * 8) * 2);
    }
    asm volatile("cp.async.commit_group;" ::: "memory");
}

// ---------------- main GEMM: 128x128 tile, 8 warps (32x64 each), K=1792 ------
__device__ __forceinline__ void gemm_main(const __nv_bfloat16* A,
                                          const __nv_bfloat16* B,
                                          uint32_t sb,
                                          float (&acc)[2][8][4]) {
    int tid = threadIdx.x, lane = tid & 31, w = tid >> 5;
    int wm = w & 3, wn = w >> 2;

    load_stage(sb, 0, A, B, 0, tid);
    load_stage(sb, 1, A, B, 64, tid);
    asm volatile("cp.async.wait_group 1;" ::: "memory");
    __syncthreads();

    for (int kt = 0; kt < KSTEPS; ++kt) {
        int s = kt % 3;
        if (kt + 2 < KSTEPS)
            load_stage(sb, (kt + 2) % 3, A, B, (kt + 2) * 64, tid);
        else
            asm volatile("cp.async.commit_group;" ::: "memory");

        uint32_t abase = sb + s * STG_BYTES;
        uint32_t bbase = abase + B_OFF;

        #pragma unroll
        for (int ks = 0; ks < 4; ++ks) {
            uint32_t afr[2][4];
            #pragma unroll
            for (int mi = 0; mi < 2; ++mi) {
                int r = wm * 32 + mi * 16 + (lane & 15);
                int c = ks * 2 + (lane >> 4);
                uint32_t addr = abase + swz(r, c);
                asm volatile("ldmatrix.sync.aligned.m8n8.x4.shared.b16 {%0,%1,%2,%3}, [%4];"
                             : "=r"(afr[mi][0]), "=r"(afr[mi][1]),
                               "=r"(afr[mi][2]), "=r"(afr[mi][3])
                             : "r"(addr));
            }
            uint32_t bfr[8][2];
            #pragma unroll
            for (int nq = 0; nq < 4; ++nq) {
                int q = lane >> 3;
                int r = wn * 64 + nq * 16 + (q >> 1) * 8 + (lane & 7);
                int c = ks * 2 + (q & 1);
                uint32_t addr = bbase + swz(r, c);
                asm volatile("ldmatrix.sync.aligned.m8n8.x4.shared.b16 {%0,%1,%2,%3}, [%4];"
                             : "=r"(bfr[nq*2][0]), "=r"(bfr[nq*2][1]),
                               "=r"(bfr[nq*2+1][0]), "=r"(bfr[nq*2+1][1])
                             : "r"(addr));
            }
            #pragma unroll
            for (int mi = 0; mi < 2; ++mi)
                #pragma unroll
                for (int ni = 0; ni < 8; ++ni)
                    asm volatile(
                        "mma.sync.aligned.m16n8k16.row.col.f32.bf16.bf16.f32 "
                        "{%0,%1,%2,%3}, {%4,%5,%6,%7}, {%8,%9}, {%0,%1,%2,%3};"
                        : "+f"(acc[mi][ni][0]), "+f"(acc[mi][ni][1]),
                          "+f"(acc[mi][ni][2]), "+f"(acc[mi][ni][3])
                        : "r"(afr[mi][0]), "r"(afr[mi][1]),
                          "r"(afr[mi][2]), "r"(afr[mi][3]),
                          "r"(bfr[ni][0]), "r"(bfr[ni][1]));
        }
        asm volatile("cp.async.wait_group 1;" ::: "memory");
        __syncthreads();
    }
}

// ---------------- prepass kernels --------------------------------------------
__global__ void convert_W(const float* __restrict__ W) {
    int o = blockIdx.x;
    for (int c = threadIdx.x; c < DIMC; c += 256)
        g_Wbf[(size_t)o * DIMC + c] = __float2bfloat16(W[(size_t)o * 1794 + c]);
}

__global__ void transpose_sample(const float* __restrict__ S) {
    __shared__ float t[32][33];
    int b = blockIdx.z;
    int hw0 = blockIdx.x * 32, c0 = blockIdx.y * 32;
    int tx = threadIdx.x, ty = threadIdx.y;
    const float* src = S + ((size_t)b * DIMC + c0) * HW + hw0;
    #pragma unroll
    for (int i = 0; i < 4; ++i)
        t[ty + i * 8][tx] = src[(size_t)(ty + i * 8) * HW + tx];
    __syncthreads();
    __nv_bfloat16* dst = g_sample_t + ((size_t)b * HW + hw0) * DIMC + c0;
    #pragma unroll
    for (int i = 0; i < 4; ++i)
        dst[(size_t)(ty + i * 8) * DIMC + tx] = __float2bfloat16(t[tx][ty + i * 8]);
}

__global__ void transpose_C(const float* __restrict__ C) {
    __shared__ float t[32][33];
    int k0 = blockIdx.x * 32, c0 = blockIdx.y * 32;
    int tx = threadIdx.x, ty = threadIdx.y;
    #pragma unroll
    for (int i = 0; i < 4; ++i)
        t[ty + i * 8][tx] = C[(size_t)(c0 + ty + i * 8) * NCENT + k0 + tx];
    __syncthreads();
    #pragma unroll
    for (int i = 0; i < 4; ++i)
        g_Ct[(size_t)(k0 + ty + i * 8) * DIMC + c0 + tx] = __float2bfloat16(t[tx][ty + i * 8]);
}

// warp-per-center, uint4 loads
__global__ void cnorm2_k() {
    int w = threadIdx.x >> 5, lane = threadIdx.x & 31;
    int k = blockIdx.x * 8 + w;
    const uint4* row = (const uint4*)(g_Ct + (size_t)k * DIMC);
    float s = 0.f;
    for (int i = lane; i < 224; i += 32) {
        uint4 v = row[i];
        const __nv_bfloat162* h = (const __nv_bfloat162*)&v;
        #pragma unroll
        for (int j = 0; j < 4; ++j) {
            float2 f = __bfloat1622float2(h[j]);
            s += f.x * f.x + f.y * f.y;
        }
    }
    #pragma unroll
    for (int o = 16; o; o >>= 1) s += __shfl_xor_sync(0xffffffffu, s, o);
    if (lane == 0) g_cnorm[k] = s;
}

// ---------------- phi GEMM (coordconv 1x1) ------------------------------------
__global__ __launch_bounds__(256, 2) void phi_mma(const float* __restrict__ W,
                                                  const float* __restrict__ bias) {
    extern __shared__ __align__(1024) unsigned char smem[];
    uint32_t sb = smem_u32(smem);
    const int n0 = blockIdx.x * 128;
    const int p0 = blockIdx.y * 128;

    float acc[2][8][4] = {};
    gemm_main(g_sample_t + (size_t)p0 * DIMC, g_Wbf + (size_t)n0 * DIMC, sb, acc);

    int tid = threadIdx.x, lane = tid & 31, w = tid >> 5;
    int wm = w & 3, wn = w >> 2, gid = lane >> 2, tq = lane & 3;

    // stage coord weights + bias in smem
    float* smw = (float*)smem;            // [128]wx [128]wy [128]b
    float* smf = (float*)(smem + 2048);   // [128][2]
    if (tid < 128) {
        size_t col = (size_t)(n0 + tid);
        smw[tid]       = __ldg(&W[col * 1794 + 1792]);
        smw[128 + tid] = __ldg(&W[col * 1794 + 1793]);
        smw[256 + tid] = __ldg(&bias[col]);
    }
    __syncthreads();

    #pragma unroll
    for (int mi = 0; mi < 2; ++mi)
        #pragma unroll
        for (int hh = 0; hh < 2; ++hh) {
            int row = wm * 32 + mi * 16 + hh * 8 + gid;
            int p = p0 + row;
            int hw = p & 4095;
            float xx = -1.f + 2.f * (float)(hw & 63) * (1.f / 63.f);
            float yy = -1.f + 2.f * (float)(hw >> 6) * (1.f / 63.f);
            float sq = 0.f;
            #pragma unroll
            for (int ni = 0; ni < 8; ++ni) {
                int ci = wn * 64 + ni * 8 + tq * 2;
                float v0 = acc[mi][ni][hh * 2]     + xx * smw[ci]   + yy * smw[128 + ci]   + smw[256 + ci];
                float v1 = acc[mi][ni][hh * 2 + 1] + xx * smw[ci+1] + yy * smw[128 + ci+1] + smw[256 + ci+1];
                __nv_bfloat162 bb = __floats2bfloat162_rn(v0, v1);
                *(uint32_t*)&g_phi_bf[(size_t)p * DIMC + n0 + ci] = *(uint32_t*)&bb;
                float f0 = __bfloat162float(bb.x), f1 = __bfloat162float(bb.y);
                sq += f0 * f0 + f1 * f1;
            }
            sq += __shfl_xor_sync(0xffffffffu, sq, 1);
            sq += __shfl_xor_sync(0xffffffffu, sq, 2);
            if (tq == 0) smf[row * 2 + wn] = sq;
        }
    __syncthreads();
    if (tid < 128)
        g_feat2p[(size_t)(p0 + tid) * NB_P + blockIdx.x] = smf[tid * 2] + smf[tid * 2 + 1];
}

__global__ void feat2_k() {
    int p = blockIdx.x * 256 + threadIdx.x;
    float s = 0.f;
    #pragma unroll
    for (int i = 0; i < NB_P; ++i) s += g_feat2p[(size_t)p * NB_P + i];
    g_feat2[p] = s;
}

// ---------------- dist GEMM + per-tile top-6 ----------------------------------
__global__ __launch_bounds__(256, 2) void dist_mma() {
    extern __shared__ __align__(1024) unsigned char smem[];
    uint32_t sb = smem_u32(smem);
    const int nb = blockIdx.x;
    const int n0 = nb * 128;
    const int p0 = blockIdx.y * 128;

    float acc[2][8][4] = {};
    gemm_main(g_phi_bf + (size_t)p0 * DIMC, g_Ct + (size_t)n0 * DIMC, sb, acc);

    int tid = threadIdx.x, lane = tid & 31, w = tid >> 5;
    int wm = w & 3, wn = w >> 2, gid = lane >> 2, tq = lane & 3;

    // hoist per-row feat2 into registers before smem staging
    float f2r[2][2];
    #pragma unroll
    for (int mi = 0; mi < 2; ++mi)
        #pragma unroll
        for (int hh = 0; hh < 2; ++hh)
            f2r[mi][hh] = g_feat2[p0 + wm * 32 + mi * 16 + hh * 8 + gid];

    float* smc = (float*)smem;                 // [128] cnorm
    float* sm_t6 = (float*)(smem + 1024);      // [128][2][6]
    if (tid < 128) smc[tid] = g_cnorm[n0 + tid];
    __syncthreads();

    #pragma unroll
    for (int mi = 0; mi < 2; ++mi)
        #pragma unroll
        for (int hh = 0; hh < 2; ++hh) {
            int row = wm * 32 + mi * 16 + hh * 8 + gid;
            float f2 = f2r[mi][hh];
            float t6[6];
            #pragma unroll
            for (int j = 0; j < 6; ++j) t6[j] = 3.4e38f;
            #pragma unroll
            for (int ni = 0; ni < 8; ++ni) {
                int ci = wn * 64 + ni * 8 + tq * 2;
                insert6(t6, f2 + smc[ci]     - 2.f * acc[mi][ni][hh * 2]);
                insert6(t6, f2 + smc[ci + 1] - 2.f * acc[mi][ni][hh * 2 + 1]);
            }
            #pragma unroll
            for (int off = 1; off <= 2; off <<= 1) {
                float o6[6];
                #pragma unroll
                for (int j = 0; j < 6; ++j) o6[j] = __shfl_xor_sync(0xffffffffu, t6[j], off);
                #pragma unroll
                for (int j = 0; j < 6; ++j) insert6(t6, o6[j]);
            }
            if (tq == 0) {
                #pragma unroll
                for (int j = 0; j < 6; ++j) sm_t6[(row * 2 + wn) * 6 + j] = t6[j];
            }
        }
    __syncthreads();
    if (tid < 128) {
        float t6[6];
        #pragma unroll
        for (int j = 0; j < 6; ++j) t6[j] = 3.4e38f;
        #pragma unroll
        for (int v = 0; v < 12; ++v) insert6(t6, sm_t6[tid * 12 + v]);
        size_t base = ((size_t)(p0 + tid) * NB_D + nb) * 6;
        #pragma unroll
        for (int j = 0; j < 6; ++j) g_cand[base + j] = t6[j];
    }
}

// ---------------- topk merge + score + loss -----------------------------------
__global__ void topk_kernel(const float* __restrict__ r_in, float* __restrict__ out) {
    int warp = threadIdx.x >> 5;
    int lane = threadIdx.x & 31;
    int p = blockIdx.x * 4 + warp;
    const float* cand = g_cand + (size_t)p * (NB_D * 6);   // 192 values

    float t6[6];
    #pragma unroll
    for (int j = 0; j < 6; ++j) t6[j] = 3.4e38f;
    #pragma unroll
    for (int j = 0; j < 6; ++j) insert6(t6, cand[lane + 32 * j]);

    #pragma unroll
    for (int off = 16; off > 0; off >>= 1) {
        float o6[6];
        #pragma unroll
        for (int j = 0; j < 6; ++j) o6[j] = __shfl_xor_sync(0xffffffffu, t6[j], off);
        #pragma unroll
        for (int j = 0; j < 6; ++j) insert6(t6, o6[j]);
    }

    if (lane == 0) {
        float rr = r_in[0];
        float r2 = rr * rr;
        float d0 = sqrtf(fmaxf(t6[0], 0.f));
        float d1 = sqrtf(fmaxf(t6[1], 0.f));
        float d2 = sqrtf(fmaxf(t6[2], 0.f));
        float w0 = 1.f / (1.f + expf(d0 - d1) + expf(d0 - d2));
        out[1 + p] = w0 * d0;

        float att = fmaxf(t6[0] - r2, 0.f) + fmaxf(t6[1] - r2, 0.f) + fmaxf(t6[2] - r2, 0.f);
        float rep = fmaxf(r2 - t6[3] - 0.1f, 0.f) + fmaxf(r2 - t6[4] - 0.1f, 0.f)
                  + fmaxf(r2 - t6[5] - 0.1f, 0.f);
        g_losspart[p] = att + rep;
    }
}

__global__ void loss_kernel(float* __restrict__ out) {
    __shared__ float sbuf[256];
    float s = 0.f;
    for (int i = threadIdx.x; i < M_TOT; i += 256) s += g_losspart[i];
    sbuf[threadIdx.x] = s;
    __syncthreads();
    for (int o = 128; o > 0; o >>= 1) {
        if (threadIdx.x < o) sbuf[threadIdx.x] += sbuf[threadIdx.x + o];
        __syncthreads();
    }
    if (threadIdx.x == 0)
        out[0] = sbuf[0] * (1000.f / (float)(M_TOT * 3));
}

// ---------------- launcher ------------------------------------------------------
extern "C" void kernel_launch(void* const* d_in, const int* in_sizes, int n_in,
                              void* d_out, int out_size) {
    const float* sample = (const float*)d_in[0];
    const float* W      = (const float*)d_in[1];
    const float* bias   = (const float*)d_in[2];
    const float* C      = (const float*)d_in[3];
    const float* r      = (const float*)d_in[4];
    float* out = (float*)d_out;

    cudaFuncSetAttribute(phi_mma, cudaFuncAttributeMaxDynamicSharedMemorySize, DYN_SMEM);
    cudaFuncSetAttribute(dist_mma, cudaFuncAttributeMaxDynamicSharedMemorySize, DYN_SMEM);

    // NOTE: launch order arranged so the GEMM (phi_mma) sits at launch index 3,
    // which is the slot ncu has been sampling — gets us a real GEMM profile.
    convert_W<<<DIMC, 256>>>(W);                                        // 0
    transpose_sample<<<dim3(HW / 32, DIMC / 32, 4), dim3(32, 8)>>>(sample); // 1
    transpose_C<<<dim3(NCENT / 32, DIMC / 32), dim3(32, 8)>>>(C);       // 2
    phi_mma<<<dim3(NB_P, M_TOT / 128), 256, DYN_SMEM>>>(W, bias);       // 3  <- profiled
    feat2_k<<<M_TOT / 256, 256>>>();                                    // 4
    cnorm2_k<<<NCENT / 8, 256>>>();                                     // 5
    dist_mma<<<dim3(NB_D, M_TOT / 128), 256, DYN_SMEM>>>();             // 6
    topk_kernel<<<M_TOT / 4, 128>>>(r, out);                            // 7
    loss_kernel<<<1, 256>>>(out);                                       // 8
}

// round 11
// speedup vs baseline: 2.0948x; 1.0114x over previous
#include <cuda_runtime.h>
#include <cuda_bf16.h>
#include <math.h>
#include <stdint.h>

#define DIMC   1792
#define M_TOT  16384        // 4 * 64 * 64
#define NCENT  4096
#define HW     4096
#define NB_D   32           // dist n-tiles of 128
#define NB_P   14           // phi  n-tiles of 128
#define KSTEPS 28           // 1792 / 64

// ---------------- scratch ---------------------------------------------------
__device__ __align__(1024) __nv_bfloat16 g_sample_t[(size_t)M_TOT * DIMC];
__device__ __align__(1024) __nv_bfloat16 g_phi_bf[(size_t)M_TOT * DIMC];
__device__ __align__(1024) __nv_bfloat16 g_Ct[(size_t)NCENT * DIMC];
__device__ __align__(1024) __nv_bfloat16 g_Wbf[(size_t)DIMC * DIMC];
__device__ float g_feat2p[M_TOT * NB_P];
__device__ float g_feat2[M_TOT];
__device__ float g_cnorm[NCENT];
__device__ float g_cand[(size_t)M_TOT * NB_D * 6];
__device__ float g_losspart[M_TOT];

// ---------------- helpers ----------------------------------------------------
__device__ __forceinline__ uint32_t smem_u32(const void* p) {
    uint32_t a;
    asm("{ .reg .u64 t; cvta.to.shared.u64 t, %1; cvt.u32.u64 %0, t; }" : "=r"(a) : "l"(p));
    return a;
}
__device__ __forceinline__ void cp16(uint32_t dst, const void* src) {
    asm volatile("cp.async.cg.shared.global [%0], [%1], 16;" :: "r"(dst), "l"(src));
}
__device__ __forceinline__ void insert6(float (&t)[6], float v) {
    if (v < t[5]) {
        t[5] = v;
        #pragma unroll
        for (int j = 5; j > 0; --j)
            if (t[j] < t[j-1]) { float tmp = t[j-1]; t[j-1] = t[j]; t[j] = tmp; }
    }
}

// stage: A(128 rows x 128B) + B(128 rows x 128B) = 32KB; 3 stages = 96KB
#define STG_BYTES 32768
#define B_OFF     16384
#define DYN_SMEM  (3 * STG_BYTES)
// full SW128 swizzle: row r (0..127, 128B pitch), 16B-chunk c (0..7)
__device__ __forceinline__ uint32_t swz(int r, int c) {
    return (uint32_t)(r * 128 + ((c ^ (r & 7)) * 16));
}

__device__ __forceinline__ void load_stage(uint32_t sb, int s,
                                           const __nv_bfloat16* A,
                                           const __nv_bfloat16* B,
                                           int k0, int tid) {
    uint32_t abase = sb + s * STG_BYTES;
    uint32_t bbase = abase + B_OFF;
    #pragma unroll
    for (int i = 0; i < 4; ++i) {           // A: 128 rows x 128B
        int slot = tid + i * 256;
        int r = slot >> 3, c = slot & 7;
        cp16(abase + swz(r, c), (const char*)A + ((size_t)r * DIMC + k0 + c * 8) * 2);
    }
    #pragma unroll
    for (int i = 0; i < 4; ++i) {           // B: 128 rows x 128B
        int slot = tid + i * 256;
        int r = slot >> 3, c = slot & 7;
        cp16(bbase + swz(r, c), (const char*)B + ((size_t)r * DIMC + k0 + c * 8) * 2);
    }
    asm volatile("cp.async.commit_group;" ::: "memory");
}

#define MMA_BF16(ac, a, b0, b1) \
    asm volatile( \
        "mma.sync.aligned.m16n8k16.row.col.f32.bf16.bf16.f32 " \
        "{%0,%1,%2,%3}, {%4,%5,%6,%7}, {%8,%9}, {%0,%1,%2,%3};" \
        : "+f"((ac)[0]), "+f"((ac)[1]), "+f"((ac)[2]), "+f"((ac)[3]) \
        : "r"((a)[0]), "r"((a)[1]), "r"((a)[2]), "r"((a)[3]), \
          "r"(b0), "r"(b1))

// ---------------- main GEMM: 128x128 tile, 8 warps (32x64 each), K=1792 ------
__device__ __forceinline__ void gemm_main(const __nv_bfloat16* A,
                                          const __nv_bfloat16* B,
                                          uint32_t sb,
                                          float (&acc)[2][8][4]) {
    int tid = threadIdx.x, lane = tid & 31, w = tid >> 5;
    int wm = w & 3, wn = w >> 2;

    load_stage(sb, 0, A, B, 0, tid);
    load_stage(sb, 1, A, B, 64, tid);
    asm volatile("cp.async.wait_group 1;" ::: "memory");
    __syncthreads();

    for (int kt = 0; kt < KSTEPS; ++kt) {
        int s = kt % 3;
        if (kt + 2 < KSTEPS)
            load_stage(sb, (kt + 2) % 3, A, B, (kt + 2) * 64, tid);
        else
            asm volatile("cp.async.commit_group;" ::: "memory");

        uint32_t abase = sb + s * STG_BYTES;
        uint32_t bbase = abase + B_OFF;

        #pragma unroll
        for (int ks = 0; ks < 4; ++ks) {
            uint32_t afr[2][4];
            #pragma unroll
            for (int mi = 0; mi < 2; ++mi) {
                int r = wm * 32 + mi * 16 + (lane & 15);
                int c = ks * 2 + (lane >> 4);
                uint32_t addr = abase + swz(r, c);
                asm volatile("ldmatrix.sync.aligned.m8n8.x4.shared.b16 {%0,%1,%2,%3}, [%4];"
                             : "=r"(afr[mi][0]), "=r"(afr[mi][1]),
                               "=r"(afr[mi][2]), "=r"(afr[mi][3])
                             : "r"(addr));
            }
            // interleave: per nq, one B ldmatrix.x4 then its 4 dependent MMAs;
            // next nq's load overlaps these MMAs.
            #pragma unroll
            for (int nq = 0; nq < 4; ++nq) {
                uint32_t b00, b01, b10, b11;
                int q = lane >> 3;
                int r = wn * 64 + nq * 16 + (q >> 1) * 8 + (lane & 7);
                int c = ks * 2 + (q & 1);
                uint32_t addr = bbase + swz(r, c);
                asm volatile("ldmatrix.sync.aligned.m8n8.x4.shared.b16 {%0,%1,%2,%3}, [%4];"
                             : "=r"(b00), "=r"(b01), "=r"(b10), "=r"(b11)
                             : "r"(addr));
                MMA_BF16(acc[0][nq * 2],     afr[0], b00, b01);
                MMA_BF16(acc[1][nq * 2],     afr[1], b00, b01);
                MMA_BF16(acc[0][nq * 2 + 1], afr[0], b10, b11);
                MMA_BF16(acc[1][nq * 2 + 1], afr[1], b10, b11);
            }
        }
        asm volatile("cp.async.wait_group 1;" ::: "memory");
        __syncthreads();
    }
}

// ---------------- prepass kernels --------------------------------------------
__global__ void convert_W(const float* __restrict__ W) {
    int o = blockIdx.x;
    for (int c = threadIdx.x; c < DIMC; c += 256)
        g_Wbf[(size_t)o * DIMC + c] = __float2bfloat16(W[(size_t)o * 1794 + c]);
}

// tile: 32 hw x 64 c; smem [hw][c] padded; bf16x2 vectorized stores (128B/warp)
__global__ void transpose_sample(const float* __restrict__ S) {
    __shared__ float t[32][65];
    int b = blockIdx.z;
    int hw0 = blockIdx.x * 32, c0 = blockIdx.y * 64;
    int tx = threadIdx.x, ty = threadIdx.y;   // (32, 8)
    const float* src = S + ((size_t)b * DIMC + c0) * HW + hw0;
    #pragma unroll
    for (int i = 0; i < 8; ++i) {
        int cr = ty + i * 8;
        t[tx][cr] = src[(size_t)cr * HW + tx];
    }
    __syncthreads();
    __nv_bfloat16* dst = g_sample_t + ((size_t)b * HW + hw0) * DIMC + c0;
    #pragma unroll
    for (int i = 0; i < 4; ++i) {
        int hw = ty + i * 8;
        __nv_bfloat162 v = __floats2bfloat162_rn(t[hw][tx * 2], t[hw][tx * 2 + 1]);
        *(__nv_bfloat162*)&dst[(size_t)hw * DIMC + tx * 2] = v;
    }
}

__global__ void transpose_C(const float* __restrict__ C) {
    __shared__ float t[32][33];
    int k0 = blockIdx.x * 32, c0 = blockIdx.y * 32;
    int tx = threadIdx.x, ty = threadIdx.y;
    #pragma unroll
    for (int i = 0; i < 4; ++i)
        t[ty + i * 8][tx] = C[(size_t)(c0 + ty + i * 8) * NCENT + k0 + tx];
    __syncthreads();
    #pragma unroll
    for (int i = 0; i < 4; ++i)
        g_Ct[(size_t)(k0 + ty + i * 8) * DIMC + c0 + tx] = __float2bfloat16(t[tx][ty + i * 8]);
}

// warp-per-center, uint4 loads
__global__ void cnorm2_k() {
    int w = threadIdx.x >> 5, lane = threadIdx.x & 31;
    int k = blockIdx.x * 8 + w;
    const uint4* row = (const uint4*)(g_Ct + (size_t)k * DIMC);
    float s = 0.f;
    for (int i = lane; i < 224; i += 32) {
        uint4 v = row[i];
        const __nv_bfloat162* h = (const __nv_bfloat162*)&v;
        #pragma unroll
        for (int j = 0; j < 4; ++j) {
            float2 f = __bfloat1622float2(h[j]);
            s += f.x * f.x + f.y * f.y;
        }
    }
    #pragma unroll
    for (int o = 16; o; o >>= 1) s += __shfl_xor_sync(0xffffffffu, s, o);
    if (lane == 0) g_cnorm[k] = s;
}

// ---------------- phi GEMM (coordconv 1x1) ------------------------------------
__global__ __launch_bounds__(256, 2) void phi_mma(const float* __restrict__ W,
                                                  const float* __restrict__ bias) {
    extern __shared__ __align__(1024) unsigned char smem[];
    uint32_t sb = smem_u32(smem);
    const int n0 = blockIdx.x * 128;
    const int p0 = blockIdx.y * 128;

    float acc[2][8][4] = {};
    gemm_main(g_sample_t + (size_t)p0 * DIMC, g_Wbf + (size_t)n0 * DIMC, sb, acc);

    int tid = threadIdx.x, lane = tid & 31, w = tid >> 5;
    int wm = w & 3, wn = w >> 2, gid = lane >> 2, tq = lane & 3;

    // stage coord weights + bias in smem
    float* smw = (float*)smem;            // [128]wx [128]wy [128]b
    float* smf = (float*)(smem + 2048);   // [128][2]
    if (tid < 128) {
        size_t col = (size_t)(n0 + tid);
        smw[tid]       = __ldg(&W[col * 1794 + 1792]);
        smw[128 + tid] = __ldg(&W[col * 1794 + 1793]);
        smw[256 + tid] = __ldg(&bias[col]);
    }
    __syncthreads();

    #pragma unroll
    for (int mi = 0; mi < 2; ++mi)
        #pragma unroll
        for (int hh = 0; hh < 2; ++hh) {
            int row = wm * 32 + mi * 16 + hh * 8 + gid;
            int p = p0 + row;
            int hw = p & 4095;
            float xx = -1.f + 2.f * (float)(hw & 63) * (1.f / 63.f);
            float yy = -1.f + 2.f * (float)(hw >> 6) * (1.f / 63.f);
            float sq = 0.f;
            #pragma unroll
            for (int ni = 0; ni < 8; ++ni) {
                int ci = wn * 64 + ni * 8 + tq * 2;
                float v0 = acc[mi][ni][hh * 2]     + xx * smw[ci]   + yy * smw[128 + ci]   + smw[256 + ci];
                float v1 = acc[mi][ni][hh * 2 + 1] + xx * smw[ci+1] + yy * smw[128 + ci+1] + smw[256 + ci+1];
                __nv_bfloat162 bb = __floats2bfloat162_rn(v0, v1);
                *(uint32_t*)&g_phi_bf[(size_t)p * DIMC + n0 + ci] = *(uint32_t*)&bb;
                float f0 = __bfloat162float(bb.x), f1 = __bfloat162float(bb.y);
                sq += f0 * f0 + f1 * f1;
            }
            sq += __shfl_xor_sync(0xffffffffu, sq, 1);
            sq += __shfl_xor_sync(0xffffffffu, sq, 2);
            if (tq == 0) smf[row * 2 + wn] = sq;
        }
    __syncthreads();
    if (tid < 128)
        g_feat2p[(size_t)(p0 + tid) * NB_P + blockIdx.x] = smf[tid * 2] + smf[tid * 2 + 1];
}

__global__ void feat2_k() {
    int p = blockIdx.x * 256 + threadIdx.x;
    float s = 0.f;
    #pragma unroll
    for (int i = 0; i < NB_P; ++i) s += g_feat2p[(size_t)p * NB_P + i];
    g_feat2[p] = s;
}

// ---------------- dist GEMM + per-tile top-6 ----------------------------------
__global__ __launch_bounds__(256, 2) void dist_mma() {
    extern __shared__ __align__(1024) unsigned char smem[];
    uint32_t sb = smem_u32(smem);
    const int nb = blockIdx.x;
    const int n0 = nb * 128;
    const int p0 = blockIdx.y * 128;

    float acc[2][8][4] = {};
    gemm_main(g_phi_bf + (size_t)p0 * DIMC, g_Ct + (size_t)n0 * DIMC, sb, acc);

    int tid = threadIdx.x, lane = tid & 31, w = tid >> 5;
    int wm = w & 3, wn = w >> 2, gid = lane >> 2, tq = lane & 3;

    // hoist per-row feat2 into registers before smem staging
    float f2r[2][2];
    #pragma unroll
    for (int mi = 0; mi < 2; ++mi)
        #pragma unroll
        for (int hh = 0; hh < 2; ++hh)
            f2r[mi][hh] = g_feat2[p0 + wm * 32 + mi * 16 + hh * 8 + gid];

    float* smc = (float*)smem;                 // [128] cnorm
    float* sm_t6 = (float*)(smem + 1024);      // [128][2][6]
    if (tid < 128) smc[tid] = g_cnorm[n0 + tid];
    __syncthreads();

    #pragma unroll
    for (int mi = 0; mi < 2; ++mi)
        #pragma unroll
        for (int hh = 0; hh < 2; ++hh) {
            int row = wm * 32 + mi * 16 + hh * 8 + gid;
            float f2 = f2r[mi][hh];
            float t6[6];
            #pragma unroll
            for (int j = 0; j < 6; ++j) t6[j] = 3.4e38f;
            #pragma unroll
            for (int ni = 0; ni < 8; ++ni) {
                int ci = wn * 64 + ni * 8 + tq * 2;
                insert6(t6, f2 + smc[ci]     - 2.f * acc[mi][ni][hh * 2]);
                insert6(t6, f2 + smc[ci + 1] - 2.f * acc[mi][ni][hh * 2 + 1]);
            }
            #pragma unroll
            for (int off = 1; off <= 2; off <<= 1) {
                float o6[6];
                #pragma unroll
                for (int j = 0; j < 6; ++j) o6[j] = __shfl_xor_sync(0xffffffffu, t6[j], off);
                #pragma unroll
                for (int j = 0; j < 6; ++j) insert6(t6, o6[j]);
            }
            if (tq == 0) {
                #pragma unroll
                for (int j = 0; j < 6; ++j) sm_t6[(row * 2 + wn) * 6 + j] = t6[j];
            }
        }
    __syncthreads();
    if (tid < 128) {
        float t6[6];
        #pragma unroll
        for (int j = 0; j < 6; ++j) t6[j] = 3.4e38f;
        #pragma unroll
        for (int v = 0; v < 12; ++v) insert6(t6, sm_t6[tid * 12 + v]);
        size_t base = ((size_t)(p0 + tid) * NB_D + nb) * 6;
        #pragma unroll
        for (int j = 0; j < 6; ++j) g_cand[base + j] = t6[j];
    }
}

// ---------------- topk merge + score + loss -----------------------------------
__global__ void topk_kernel(const float* __restrict__ r_in, float* __restrict__ out) {
    int warp = threadIdx.x >> 5;
    int lane = threadIdx.x & 31;
    int p = blockIdx.x * 4 + warp;
    const float* cand = g_cand + (size_t)p * (NB_D * 6);   // 192 values

    float t6[6];
    #pragma unroll
    for (int j = 0; j < 6; ++j) t6[j] = 3.4e38f;
    #pragma unroll
    for (int j = 0; j < 6; ++j) insert6(t6, cand[lane + 32 * j]);

    #pragma unroll
    for (int off = 16; off > 0; off >>= 1) {
        float o6[6];
        #pragma unroll
        for (int j = 0; j < 6; ++j) o6[j] = __shfl_xor_sync(0xffffffffu, t6[j], off);
        #pragma unroll
        for (int j = 0; j < 6; ++j) insert6(t6, o6[j]);
    }

    if (lane == 0) {
        float rr = r_in[0];
        float r2 = rr * rr;
        float d0 = sqrtf(fmaxf(t6[0], 0.f));
        float d1 = sqrtf(fmaxf(t6[1], 0.f));
        float d2 = sqrtf(fmaxf(t6[2], 0.f));
        float w0 = 1.f / (1.f + expf(d0 - d1) + expf(d0 - d2));
        out[1 + p] = w0 * d0;

        float att = fmaxf(t6[0] - r2, 0.f) + fmaxf(t6[1] - r2, 0.f) + fmaxf(t6[2] - r2, 0.f);
        float rep = fmaxf(r2 - t6[3] - 0.1f, 0.f) + fmaxf(r2 - t6[4] - 0.1f, 0.f)
                  + fmaxf(r2 - t6[5] - 0.1f, 0.f);
        g_losspart[p] = att + rep;
    }
}

__global__ void loss_kernel(float* __restrict__ out) {
    __shared__ float sbuf[256];
    float s = 0.f;
    for (int i = threadIdx.x; i < M_TOT; i += 256) s += g_losspart[i];
    sbuf[threadIdx.x] = s;
    __syncthreads();
    for (int o = 128; o > 0; o >>= 1) {
        if (threadIdx.x < o) sbuf[threadIdx.x] += sbuf[threadIdx.x + o];
        __syncthreads();
    }
    if (threadIdx.x == 0)
        out[0] = sbuf[0] * (1000.f / (float)(M_TOT * 3));
}

// ---------------- launcher ------------------------------------------------------
extern "C" void kernel_launch(void* const* d_in, const int* in_sizes, int n_in,
                              void* d_out, int out_size) {
    const float* sample = (const float*)d_in[0];
    const float* W      = (const float*)d_in[1];
    const float* bias   = (const float*)d_in[2];
    const float* C      = (const float*)d_in[3];
    const float* r      = (const float*)d_in[4];
    float* out = (float*)d_out;

    cudaFuncSetAttribute(phi_mma, cudaFuncAttributeMaxDynamicSharedMemorySize, DYN_SMEM);
    cudaFuncSetAttribute(dist_mma, cudaFuncAttributeMaxDynamicSharedMemorySize, DYN_SMEM);

    // phi_mma stays at launch index 3 (the ncu sampling slot)
    convert_W<<<DIMC, 256>>>(W);                                        // 0
    transpose_sample<<<dim3(HW / 32, DIMC / 64, 4), dim3(32, 8)>>>(sample); // 1
    transpose_C<<<dim3(NCENT / 32, DIMC / 32), dim3(32, 8)>>>(C);       // 2
    phi_mma<<<dim3(NB_P, M_TOT / 128), 256, DYN_SMEM>>>(W, bias);       // 3  <- profiled
    feat2_k<<<M_TOT / 256, 256>>>();                                    // 4
    cnorm2_k<<<NCENT / 8, 256>>>();                                     // 5
    dist_mma<<<dim3(NB_D, M_TOT / 128), 256, DYN_SMEM>>>();             // 6
    topk_kernel<<<M_TOT / 4, 128>>>(r, out);                            // 7
    loss_kernel<<<1, 256>>>(out);                                       // 8
}